// round 13
// baseline (speedup 1.0000x reference)
#include <cuda_runtime.h>
#include <cuda_fp16.h>
#include <math.h>
#include <stdint.h>

#define D_MODEL 768
#define N_HEADS 12
#define HEAD_DIM 64
#define SEQ 2048
#define BATCH 2
#define QKV_N (3 * D_MODEL)
#define M_TOK (BATCH * SEQ)
#define SCALE_LOG2E 0.18033688011112042f   // 0.125 * log2(e)

// Scratch (allocation-free rule: __device__ globals)
__device__ float g_qkv[(size_t)M_TOK * QKV_N];    // [B*S, 3*D] (Q | K | V)
__device__ float g_attn[(size_t)M_TOK * D_MODEL]; // [B*S, D] attention output

__device__ __forceinline__ uint32_t pack_h2(float lo, float hi) {
    __half2 h = __floats2half2_rn(lo, hi);
    return *reinterpret_cast<uint32_t*>(&h);
}

__device__ __forceinline__ float fexp2(float x) {
    float r;
    asm("ex2.approx.f32 %0, %1;" : "=f"(r) : "f"(x));
    return r;
}

// fp16 mma m16n8k16, fp32 accumulate
__device__ __forceinline__ void mma_f16(float* c, const uint32_t* a, const uint32_t* b) {
    asm volatile("mma.sync.aligned.m16n8k16.row.col.f32.f16.f16.f32 "
                 "{%0,%1,%2,%3}, {%4,%5,%6,%7}, {%8,%9}, {%0,%1,%2,%3};"
                 : "+f"(c[0]), "+f"(c[1]), "+f"(c[2]), "+f"(c[3])
                 : "r"(a[0]), "r"(a[1]), "r"(a[2]), "r"(a[3]),
                   "r"(b[0]), "r"(b[1]));
}

// permuted slot for k-half-pair p within each group of 8 pairs:
// [p0 p4 p1 p5 p2 p6 p3 p7] -> pairs (t, t+4) are adjacent -> uint2 loads
__device__ __host__ constexpr int pslot(int p) {
    return 8 * (p >> 3) + (((p & 7) < 4) ? 2 * (p & 7) : 2 * (p & 7) - 7);
}

// ---------------------------------------------------------------------------
// fp16 tensor-core GEMM: block 128x128x16, 128 threads = 4 warps (2Mx2N),
// warp tile 64x64, ONE m16n8k16 k-step per tile (32 mma). Double-buffered.
// A: [row][8 half2 pair-permuted]; B: [n][8 half2 (k-pairs) pair-permuted].
// ---------------------------------------------------------------------------
#define BKG 16
#define AS_STRIDE 24               // uint32 (half2) per A row (8 used)
#define BS_STRIDE 24               // uint32 per B n-row (8 used)
#define AS_TILE (128 * AS_STRIDE)
#define BS_TILE (128 * BS_STRIDE)
#define GEMM_SMEM ((2 * AS_TILE + 2 * BS_TILE) * 4)   // 49152 B

__global__ __launch_bounds__(128) void gemm_f16(const float* __restrict__ A,
                                                const float* __restrict__ B,
                                                const float* __restrict__ bias,
                                                float* __restrict__ C,
                                                int M, int N, int K)
{
    extern __shared__ uint32_t smu[];
    uint32_t* As0 = smu;
    uint32_t* As1 = As0 + AS_TILE;
    uint32_t* Bs0 = As1 + AS_TILE;
    uint32_t* Bs1 = Bs0 + BS_TILE;

    const int tid  = threadIdx.x;
    const int lane = tid & 31;
    const int wid  = tid >> 5;        // 0..3
    const int wm   = (wid & 1) * 64;
    const int wn   = (wid >> 1) * 64;
    const int row0 = blockIdx.y * 128;
    const int col0 = blockIdx.x * 128;
    const int gid  = lane >> 2;
    const int tig  = lane & 3;

    // A: 128x16 fp32 = 512 float4, 4/thread
    const float* Ag[4];
    int as0[4], as1[4];
    #pragma unroll
    for (int i = 0; i < 4; i++) {
        const int idx = tid + i * 128;
        const int ar  = idx >> 2;
        const int ak4 = (idx & 3) * 4;
        Ag[i]  = A + (size_t)(row0 + ar) * K + ak4;
        as0[i] = ar * AS_STRIDE + pslot(ak4 >> 1);
        as1[i] = ar * AS_STRIDE + pslot((ak4 >> 1) + 1);
    }
    // B: 8 k-pairs x 32 n4-groups = 256 units, 2/thread (each loads 2 rows)
    const float* Bg[2];
    int bs0[2];
    #pragma unroll
    for (int i = 0; i < 2; i++) {
        const int u  = tid + i * 128;
        const int kp = u >> 5;
        const int n4 = (u & 31) * 4;
        Bg[i]  = B + (size_t)(2 * kp) * N + col0 + n4;
        bs0[i] = n4 * BS_STRIDE + pslot(kp);
    }

    float4 pa[4], pbl[2], pbh[2];
    #pragma unroll
    for (int i = 0; i < 4; i++) pa[i] = *(const float4*)Ag[i];
    #pragma unroll
    for (int i = 0; i < 2; i++) {
        pbl[i] = *(const float4*)Bg[i];
        pbh[i] = *(const float4*)(Bg[i] + N);
    }
    #pragma unroll
    for (int i = 0; i < 4; i++) {
        As0[as0[i]] = pack_h2(pa[i].x, pa[i].y);
        As0[as1[i]] = pack_h2(pa[i].z, pa[i].w);
    }
    #pragma unroll
    for (int i = 0; i < 2; i++) {
        const float* lo = (const float*)&pbl[i];
        const float* hi = (const float*)&pbh[i];
        #pragma unroll
        for (int j = 0; j < 4; j++)
            Bs0[bs0[i] + j * BS_STRIDE] = pack_h2(lo[j], hi[j]);
    }
    __syncthreads();

    float c[4][8][4] = {};
    const int nkt = K / BKG;
    uint32_t *Acur = As0, *Anxt = As1, *Bcur = Bs0, *Bnxt = Bs1;

    for (int t = 0; t < nkt; t++) {
        if (t + 1 < nkt) {
            #pragma unroll
            for (int i = 0; i < 4; i++)
                pa[i] = *(const float4*)(Ag[i] + (t + 1) * BKG);
            #pragma unroll
            for (int i = 0; i < 2; i++) {
                pbl[i] = *(const float4*)(Bg[i] + (size_t)(t + 1) * BKG * N);
                pbh[i] = *(const float4*)(Bg[i] + (size_t)(t + 1) * BKG * N + N);
            }
        }

        // one k16 step: 32 mma
        {
            uint32_t af[4][4], bf[8][2];
            const uint32_t* Ap = Acur + (wm + gid) * AS_STRIDE + 2 * tig;
            #pragma unroll
            for (int mt = 0; mt < 4; mt++) {
                const uint2 lo = *(const uint2*)(Ap + mt * 16 * AS_STRIDE);
                const uint2 hi = *(const uint2*)(Ap + mt * 16 * AS_STRIDE + 8 * AS_STRIDE);
                af[mt][0] = lo.x; af[mt][1] = hi.x;
                af[mt][2] = lo.y; af[mt][3] = hi.y;
            }
            const uint32_t* Bp = Bcur + (wn + gid) * BS_STRIDE + 2 * tig;
            #pragma unroll
            for (int nt = 0; nt < 8; nt++) {
                const uint2 v = *(const uint2*)(Bp + nt * 8 * BS_STRIDE);
                bf[nt][0] = v.x; bf[nt][1] = v.y;
            }
            #pragma unroll
            for (int mt = 0; mt < 4; mt++)
                #pragma unroll
                for (int nt = 0; nt < 8; nt++)
                    mma_f16(c[mt][nt], af[mt], bf[nt]);
        }

        if (t + 1 < nkt) {
            #pragma unroll
            for (int i = 0; i < 4; i++) {
                Anxt[as0[i]] = pack_h2(pa[i].x, pa[i].y);
                Anxt[as1[i]] = pack_h2(pa[i].z, pa[i].w);
            }
            #pragma unroll
            for (int i = 0; i < 2; i++) {
                const float* lo = (const float*)&pbl[i];
                const float* hi = (const float*)&pbh[i];
                #pragma unroll
                for (int j = 0; j < 4; j++)
                    Bnxt[bs0[i] + j * BS_STRIDE] = pack_h2(lo[j], hi[j]);
            }
            __syncthreads();
            uint32_t* tmp;
            tmp = Acur; Acur = Anxt; Anxt = tmp;
            tmp = Bcur; Bcur = Bnxt; Bnxt = tmp;
        }
    }

    #pragma unroll
    for (int nt = 0; nt < 8; nt++) {
        const int cc = col0 + wn + nt * 8 + 2 * tig;
        const float b0 = bias ? bias[cc]     : 0.f;
        const float b1 = bias ? bias[cc + 1] : 0.f;
        #pragma unroll
        for (int mt = 0; mt < 4; mt++) {
            const int r = row0 + wm + mt * 16 + gid;
            float2 v0 = make_float2(c[mt][nt][0] + b0, c[mt][nt][1] + b1);
            float2 v1 = make_float2(c[mt][nt][2] + b0, c[mt][nt][3] + b1);
            *(float2*)&C[(size_t)r * N + cc]       = v0;
            *(float2*)&C[(size_t)(r + 8) * N + cc] = v1;
        }
    }
}

// ---------------------------------------------------------------------------
// FA2-style fp16 tensor-core causal flash attention. 256 threads = 8 warps.
// Q tile 256 rows; warp tile 32x64 (2 m-subtiles). Softmax warp-private
// (exp2 domain). P packed straight from S accumulators into fp16 a-fragments
// (2 floats per cvt). Q/K: [row][pair-permuted half2 of d]; V: [d][pair-
// permuted half2 of j]. All uint2 fragment loads conflict-free (stride 40).
// ---------------------------------------------------------------------------
#define FSTR 40
#define QROWS 256
#define FLASH_SMEM ((QROWS + 64 + 64) * FSTR * 4)   // 61440 B

__global__ __launch_bounds__(256) void flash_f16(const float* __restrict__ qkv,
                                                 float* __restrict__ out)
{
    extern __shared__ uint32_t smu[];
    uint32_t* Qt = smu;                  // [256 r][FSTR]
    uint32_t* Kt = Qt + QROWS * FSTR;    // [64 j][FSTR]
    uint32_t* Vt = Kt + 64 * FSTR;       // [64 d][FSTR]  (V^T, j-pairs in half2)

    const int tid  = threadIdx.x;
    const int lane = tid & 31;
    const int wid  = tid >> 5;          // 0..7
    const int wm   = wid * 32;
    const int gid  = lane >> 2;
    const int tig  = lane & 3;
    const int qt   = gridDim.x - 1 - blockIdx.x;  // heavy blocks first
    const int h    = blockIdx.y;
    const int b    = blockIdx.z;

    // --- Q tile: 1 thread/row, scale by SCALE*log2e, fp16 pair-permuted ---
    {
        const float* qrow = qkv + ((size_t)(b * SEQ + qt * QROWS + tid)) * QKV_N + h * HEAD_DIM;
        #pragma unroll
        for (int it = 0; it < 16; it++) {
            float4 v = *(const float4*)(qrow + it * 4);
            Qt[tid * FSTR + pslot(2 * it)]     = pack_h2(v.x * SCALE_LOG2E, v.y * SCALE_LOG2E);
            Qt[tid * FSTR + pslot(2 * it + 1)] = pack_h2(v.z * SCALE_LOG2E, v.w * SCALE_LOG2E);
        }
    }

    // --- K/V register prefetch (4 threads/row, 16 els each) ---
    const int r63 = tid & 63;
    const int cg0 = tid >> 6;           // 0..3
    float4 ka[4], va[4];
    {
        const float* kb = qkv + ((size_t)(b * SEQ + r63)) * QKV_N + D_MODEL + h * HEAD_DIM;
        #pragma unroll
        for (int it = 0; it < 4; it++) {
            const int d4 = cg0 * 16 + it * 4;
            ka[it] = *(const float4*)(kb + d4);
            va[it] = *(const float4*)(kb + D_MODEL + d4);
        }
    }

    float co[2][8][4] = {};    // O fragments: 2 m-subtiles x 8 d-tiles
    float m[4], l[4];          // [s*2+g]: subtile s, row-group g (gid / gid+8)
    #pragma unroll
    for (int i = 0; i < 4; i++) { m[i] = -1e30f; l[i] = 0.f; }

    const int rbase = qt * QROWS + wm + gid;
    const int ktmax = 4 * qt + 3;
    __half* Vh = (__half*)Vt;
    const int vcol = 2 * pslot(r63 >> 1) + (r63 & 1);   // half column within V row

    for (int kt = 0; kt <= ktmax; kt++) {
        __syncthreads();  // previous tile's consumers done with Kt/Vt

        // store K (pair-permuted half2 of d) and V^T (halves, j-permuted)
        #pragma unroll
        for (int it = 0; it < 4; it++) {
            const int d4 = cg0 * 16 + it * 4;
            const int p0 = d4 >> 1;
            Kt[r63 * FSTR + pslot(p0)]     = pack_h2(ka[it].x, ka[it].y);
            Kt[r63 * FSTR + pslot(p0 + 1)] = pack_h2(ka[it].z, ka[it].w);
            Vh[(d4 + 0) * (2 * FSTR) + vcol] = __float2half_rn(va[it].x);
            Vh[(d4 + 1) * (2 * FSTR) + vcol] = __float2half_rn(va[it].y);
            Vh[(d4 + 2) * (2 * FSTR) + vcol] = __float2half_rn(va[it].z);
            Vh[(d4 + 3) * (2 * FSTR) + vcol] = __float2half_rn(va[it].w);
        }
        __syncthreads();

        // prefetch next K/V tile into registers
        if (kt < ktmax) {
            const float* kb = qkv + ((size_t)(b * SEQ + (kt + 1) * 64 + r63)) * QKV_N
                              + D_MODEL + h * HEAD_DIM;
            #pragma unroll
            for (int it = 0; it < 4; it++) {
                const int d4 = cg0 * 16 + it * 4;
                ka[it] = *(const float4*)(kb + d4);
                va[it] = *(const float4*)(kb + D_MODEL + d4);
            }
        }

        // --- S = Q K^T (log2-domain scores), 4 k16-steps ---
        float cs[2][8][4] = {};
        #pragma unroll
        for (int ks = 0; ks < 4; ks++) {
            uint32_t af[2][4];
            #pragma unroll
            for (int s = 0; s < 2; s++) {
                const uint2 qlo = *(const uint2*)&Qt[(wm + s * 16 + gid) * FSTR + ks * 8 + 2 * tig];
                const uint2 qhi = *(const uint2*)&Qt[(wm + s * 16 + gid + 8) * FSTR + ks * 8 + 2 * tig];
                af[s][0] = qlo.x; af[s][1] = qhi.x;
                af[s][2] = qlo.y; af[s][3] = qhi.y;
            }
            #pragma unroll
            for (int nt = 0; nt < 8; nt++) {
                const uint2 kb2 = *(const uint2*)&Kt[(nt * 8 + gid) * FSTR + ks * 8 + 2 * tig];
                uint32_t bf[2] = { kb2.x, kb2.y };
                mma_f16(cs[0][nt], af[0], bf);
                mma_f16(cs[1][nt], af[1], bf);
            }
        }

        // --- causal mask (diagonal-band tiles only) ---
        if (kt >= 4 * qt) {
            #pragma unroll
            for (int s = 0; s < 2; s++) {
                const int r0 = rbase + s * 16;
                const int r1 = r0 + 8;
                #pragma unroll
                for (int nt = 0; nt < 8; nt++) {
                    const int j0 = kt * 64 + nt * 8 + 2 * tig;
                    if (j0     > r0) cs[s][nt][0] = -1e30f;
                    if (j0 + 1 > r0) cs[s][nt][1] = -1e30f;
                    if (j0     > r1) cs[s][nt][2] = -1e30f;
                    if (j0 + 1 > r1) cs[s][nt][3] = -1e30f;
                }
            }
        }

        // --- warp-private online softmax (exp2 domain, quad reductions) ---
        #pragma unroll
        for (int s = 0; s < 2; s++) {
            float tm0 = -1e30f, tm1 = -1e30f;
            #pragma unroll
            for (int nt = 0; nt < 8; nt++) {
                tm0 = fmaxf(tm0, fmaxf(cs[s][nt][0], cs[s][nt][1]));
                tm1 = fmaxf(tm1, fmaxf(cs[s][nt][2], cs[s][nt][3]));
            }
            tm0 = fmaxf(tm0, __shfl_xor_sync(0xFFFFFFFFu, tm0, 1));
            tm0 = fmaxf(tm0, __shfl_xor_sync(0xFFFFFFFFu, tm0, 2));
            tm1 = fmaxf(tm1, __shfl_xor_sync(0xFFFFFFFFu, tm1, 1));
            tm1 = fmaxf(tm1, __shfl_xor_sync(0xFFFFFFFFu, tm1, 2));

            const float mn0 = fmaxf(m[s * 2 + 0], tm0);
            const float mn1 = fmaxf(m[s * 2 + 1], tm1);
            const float al0 = fexp2(m[s * 2 + 0] - mn0);
            const float al1 = fexp2(m[s * 2 + 1] - mn1);
            m[s * 2 + 0] = mn0; m[s * 2 + 1] = mn1;

            float rs0 = 0.f, rs1 = 0.f;
            #pragma unroll
            for (int nt = 0; nt < 8; nt++) {
                cs[s][nt][0] = fexp2(cs[s][nt][0] - mn0);
                cs[s][nt][1] = fexp2(cs[s][nt][1] - mn0);
                cs[s][nt][2] = fexp2(cs[s][nt][2] - mn1);
                cs[s][nt][3] = fexp2(cs[s][nt][3] - mn1);
                rs0 += cs[s][nt][0] + cs[s][nt][1];
                rs1 += cs[s][nt][2] + cs[s][nt][3];
            }
            rs0 += __shfl_xor_sync(0xFFFFFFFFu, rs0, 1);
            rs0 += __shfl_xor_sync(0xFFFFFFFFu, rs0, 2);
            rs1 += __shfl_xor_sync(0xFFFFFFFFu, rs1, 1);
            rs1 += __shfl_xor_sync(0xFFFFFFFFu, rs1, 2);
            l[s * 2 + 0] = l[s * 2 + 0] * al0 + rs0;
            l[s * 2 + 1] = l[s * 2 + 1] * al1 + rs1;

            #pragma unroll
            for (int nt = 0; nt < 8; nt++) {
                co[s][nt][0] *= al0; co[s][nt][1] *= al0;
                co[s][nt][2] *= al1; co[s][nt][3] *= al1;
            }
        }

        // --- O += P V: P packed from S accumulators (fp16 a-fragments) ---
        #pragma unroll
        for (int ks = 0; ks < 4; ks++) {
            uint32_t pf[2][4];
            #pragma unroll
            for (int s = 0; s < 2; s++) {
                pf[s][0] = pack_h2(cs[s][2 * ks][0],     cs[s][2 * ks][1]);
                pf[s][1] = pack_h2(cs[s][2 * ks][2],     cs[s][2 * ks][3]);
                pf[s][2] = pack_h2(cs[s][2 * ks + 1][0], cs[s][2 * ks + 1][1]);
                pf[s][3] = pack_h2(cs[s][2 * ks + 1][2], cs[s][2 * ks + 1][3]);
            }
            #pragma unroll
            for (int nt = 0; nt < 8; nt++) {
                const uint2 vb2 = *(const uint2*)&Vt[(nt * 8 + gid) * FSTR + ks * 8 + 2 * tig];
                uint32_t bf[2] = { vb2.x, vb2.y };
                mma_f16(co[0][nt], pf[0], bf);
                mma_f16(co[1][nt], pf[1], bf);
            }
        }
    }

    // --- epilogue ---
    float* ob = out + ((size_t)(b * SEQ + qt * QROWS)) * D_MODEL + h * HEAD_DIM;
    #pragma unroll
    for (int s = 0; s < 2; s++) {
        const float inv0 = 1.f / l[s * 2 + 0];
        const float inv1 = 1.f / l[s * 2 + 1];
        #pragma unroll
        for (int nt = 0; nt < 8; nt++) {
            const int cc = nt * 8 + 2 * tig;
            float2 v0 = make_float2(co[s][nt][0] * inv0, co[s][nt][1] * inv0);
            float2 v1 = make_float2(co[s][nt][2] * inv1, co[s][nt][3] * inv1);
            *(float2*)&ob[(size_t)(wm + s * 16 + gid) * D_MODEL + cc]     = v0;
            *(float2*)&ob[(size_t)(wm + s * 16 + gid + 8) * D_MODEL + cc] = v1;
        }
    }
}

// ---------------------------------------------------------------------------
// Launch: fp16 QKV GEMM -> fp16 flash attention -> fp16 out projection (+bias)
// Inputs: x, attn_mask (ignored; causal known), W_qkv, W_proj, b_proj
// ---------------------------------------------------------------------------
extern "C" void kernel_launch(void* const* d_in, const int* in_sizes, int n_in,
                              void* d_out, int out_size)
{
    (void)in_sizes; (void)n_in; (void)out_size;
    const float* x      = (const float*)d_in[0];
    const float* W_qkv  = (const float*)d_in[2];
    const float* W_proj = (const float*)d_in[3];
    const float* b_proj = (const float*)d_in[4];
    float* out = (float*)d_out;

    float *qkv, *attn;
    cudaGetSymbolAddress((void**)&qkv,  g_qkv);
    cudaGetSymbolAddress((void**)&attn, g_attn);

    cudaFuncSetAttribute(gemm_f16, cudaFuncAttributeMaxDynamicSharedMemorySize, GEMM_SMEM);
    cudaFuncSetAttribute(flash_f16, cudaFuncAttributeMaxDynamicSharedMemorySize, FLASH_SMEM);

    // 1) QKV projection: [4096,768] @ [768,2304]  (fp16 tensor cores)
    gemm_f16<<<dim3(QKV_N / 128, M_TOK / 128), 128, GEMM_SMEM>>>(x, W_qkv, nullptr, qkv,
                                                                 M_TOK, QKV_N, D_MODEL);

    // 2) causal flash attention per (q-tile, head, batch)  (fp16 tensor cores)
    flash_f16<<<dim3(SEQ / QROWS, N_HEADS, BATCH), 256, FLASH_SMEM>>>(qkv, attn);

    // 3) output projection + bias: [4096,768] @ [768,768]  (fp16 tensor cores)
    gemm_f16<<<dim3(D_MODEL / 128, M_TOK / 128), 128, GEMM_SMEM>>>(attn, W_proj, b_proj, out,
                                                                   M_TOK, D_MODEL, D_MODEL);
}

// round 14
// speedup vs baseline: 1.2888x; 1.2888x over previous
#include <cuda_runtime.h>
#include <cuda_fp16.h>
#include <math.h>
#include <stdint.h>

#define D_MODEL 768
#define N_HEADS 12
#define HEAD_DIM 64
#define SEQ 2048
#define BATCH 2
#define QKV_N (3 * D_MODEL)
#define M_TOK (BATCH * SEQ)
#define SCALE_LOG2E 0.18033688011112042f   // 0.125 * log2(e)

// Scratch (allocation-free rule: __device__ globals)
__device__ float g_qkv[(size_t)M_TOK * QKV_N];    // [B*S, 3*D] (Q | K | V)
__device__ float g_attn[(size_t)M_TOK * D_MODEL]; // [B*S, D] attention output

__device__ __forceinline__ uint32_t f2tf32(float x) {
    uint32_t r;
    asm("cvt.rna.tf32.f32 %0, %1;" : "=r"(r) : "f"(x));
    return r;
}

__device__ __forceinline__ uint32_t pack_h2(float lo, float hi) {
    __half2 h = __floats2half2_rn(lo, hi);
    return *reinterpret_cast<uint32_t*>(&h);
}

__device__ __forceinline__ float fexp2(float x) {
    float r;
    asm("ex2.approx.f32 %0, %1;" : "=f"(r) : "f"(x));
    return r;
}

__device__ __forceinline__ void mma_tf32(float* c, const uint32_t* a, const uint32_t* b) {
    asm volatile("mma.sync.aligned.m16n8k8.row.col.f32.tf32.tf32.f32 "
                 "{%0,%1,%2,%3}, {%4,%5,%6,%7}, {%8,%9}, {%0,%1,%2,%3};"
                 : "+f"(c[0]), "+f"(c[1]), "+f"(c[2]), "+f"(c[3])
                 : "r"(a[0]), "r"(a[1]), "r"(a[2]), "r"(a[3]),
                   "r"(b[0]), "r"(b[1]));
}

// fp16 mma m16n8k16, fp32 accumulate
__device__ __forceinline__ void mma_f16(float* c, const uint32_t* a, const uint32_t* b) {
    asm volatile("mma.sync.aligned.m16n8k16.row.col.f32.f16.f16.f32 "
                 "{%0,%1,%2,%3}, {%4,%5,%6,%7}, {%8,%9}, {%0,%1,%2,%3};"
                 : "+f"(c[0]), "+f"(c[1]), "+f"(c[2]), "+f"(c[3])
                 : "r"(a[0]), "r"(a[1]), "r"(a[2]), "r"(a[3]),
                   "r"(b[0]), "r"(b[1]));
}

// permuted slot for pair p within each group of 8:
// [p0 p4 p1 p5 p2 p6 p3 p7] -> pairs (t, t+4) adjacent -> uint2 loads
__device__ __host__ constexpr int pslot(int p) {
    return 8 * (p >> 3) + (((p & 7) < 4) ? 2 * (p & 7) : 2 * (p & 7) - 7);
}

// ---------------------------------------------------------------------------
// tf32 tensor-core GEMM (round-11 measured best: 127us QKV): block 128x128x16,
// 128 threads = 4 warps (2Mx2N), warp tile 64x64, double-buffered.
// ---------------------------------------------------------------------------
#define BKG 16
#define AS_STRIDE 20
#define BS_STRIDE 132
#define AS_TILE (128 * AS_STRIDE)
#define BS_TILE (BKG * BS_STRIDE)
#define GEMM_SMEM ((2 * AS_TILE + 2 * BS_TILE) * 4)  // 37376 B

__global__ __launch_bounds__(128) void gemm_tf32(const float* __restrict__ A,
                                                 const float* __restrict__ B,
                                                 const float* __restrict__ bias,
                                                 float* __restrict__ C,
                                                 int M, int N, int K)
{
    extern __shared__ uint32_t smu[];
    uint32_t* As = smu;               // [2][128][20]
    uint32_t* Bs = smu + 2 * AS_TILE; // [2][16][132]

    const int tid  = threadIdx.x;
    const int lane = tid & 31;
    const int wid  = tid >> 5;        // 0..3
    const int wm   = (wid & 1) * 64;
    const int wn   = (wid >> 1) * 64;
    const int row0 = blockIdx.y * 128;
    const int col0 = blockIdx.x * 128;
    const int gid  = lane >> 2;
    const int tig  = lane & 3;

    float4 pa[4], pb[4];

    #pragma unroll
    for (int i = 0; i < 4; i++) {
        const int idx = tid + i * 128;
        pa[i] = *(const float4*)&A[(size_t)(row0 + (idx >> 2)) * K + (idx & 3) * 4];
        pb[i] = *(const float4*)&B[(size_t)(idx >> 5) * N + col0 + (idx & 31) * 4];
    }
    #pragma unroll
    for (int i = 0; i < 4; i++) {
        const int idx = tid + i * 128;
        uint32_t* p = As + (idx >> 2) * AS_STRIDE + (idx & 3) * 4;
        p[0] = f2tf32(pa[i].x); p[1] = f2tf32(pa[i].y);
        p[2] = f2tf32(pa[i].z); p[3] = f2tf32(pa[i].w);
        uint32_t* q = Bs + (idx >> 5) * BS_STRIDE + (idx & 31) * 4;
        q[0] = f2tf32(pb[i].x); q[1] = f2tf32(pb[i].y);
        q[2] = f2tf32(pb[i].z); q[3] = f2tf32(pb[i].w);
    }
    __syncthreads();

    float c[4][8][4] = {};
    const int nkt = K / BKG;
    int buf = 0;

    for (int t = 0; t < nkt; t++) {
        if (t + 1 < nkt) {
            const int k0 = (t + 1) * BKG;
            #pragma unroll
            for (int i = 0; i < 4; i++) {
                const int idx = tid + i * 128;
                pa[i] = *(const float4*)&A[(size_t)(row0 + (idx >> 2)) * K + k0 + (idx & 3) * 4];
                pb[i] = *(const float4*)&B[(size_t)(k0 + (idx >> 5)) * N + col0 + (idx & 31) * 4];
            }
        }

        #pragma unroll
        for (int ks = 0; ks < 2; ks++) {
            uint32_t af[4][4], bf[8][2];
            const uint32_t* Ab = As + buf * AS_TILE + (wm + gid) * AS_STRIDE + ks * 8 + tig;
            #pragma unroll
            for (int mt = 0; mt < 4; mt++) {
                const uint32_t* p = Ab + mt * 16 * AS_STRIDE;
                af[mt][0] = p[0];
                af[mt][1] = p[8 * AS_STRIDE];
                af[mt][2] = p[4];
                af[mt][3] = p[8 * AS_STRIDE + 4];
            }
            const uint32_t* Bb = Bs + buf * BS_TILE + (ks * 8 + tig) * BS_STRIDE + wn + gid;
            #pragma unroll
            for (int nt = 0; nt < 8; nt++) {
                const uint32_t* p = Bb + nt * 8;
                bf[nt][0] = p[0];
                bf[nt][1] = p[4 * BS_STRIDE];
            }
            #pragma unroll
            for (int mt = 0; mt < 4; mt++)
                #pragma unroll
                for (int nt = 0; nt < 8; nt++)
                    mma_tf32(c[mt][nt], af[mt], bf[nt]);
        }

        if (t + 1 < nkt) {
            buf ^= 1;
            #pragma unroll
            for (int i = 0; i < 4; i++) {
                const int idx = tid + i * 128;
                uint32_t* p = As + buf * AS_TILE + (idx >> 2) * AS_STRIDE + (idx & 3) * 4;
                p[0] = f2tf32(pa[i].x); p[1] = f2tf32(pa[i].y);
                p[2] = f2tf32(pa[i].z); p[3] = f2tf32(pa[i].w);
                uint32_t* q = Bs + buf * BS_TILE + (idx >> 5) * BS_STRIDE + (idx & 31) * 4;
                q[0] = f2tf32(pb[i].x); q[1] = f2tf32(pb[i].y);
                q[2] = f2tf32(pb[i].z); q[3] = f2tf32(pb[i].w);
            }
            __syncthreads();
        }
    }

    #pragma unroll
    for (int nt = 0; nt < 8; nt++) {
        const int cc = col0 + wn + nt * 8 + 2 * tig;
        const float b0 = bias ? bias[cc]     : 0.f;
        const float b1 = bias ? bias[cc + 1] : 0.f;
        #pragma unroll
        for (int mt = 0; mt < 4; mt++) {
            const int r = row0 + wm + mt * 16 + gid;
            float2 v0 = make_float2(c[mt][nt][0] + b0, c[mt][nt][1] + b1);
            float2 v1 = make_float2(c[mt][nt][2] + b0, c[mt][nt][3] + b1);
            *(float2*)&C[(size_t)r * N + cc]       = v0;
            *(float2*)&C[(size_t)(r + 8) * N + cc] = v1;
        }
    }
}

// ---------------------------------------------------------------------------
// FA2-style fp16 flash attention (round-13 measured best: ~179us).
// 256 threads = 8 warps; Q tile 256 rows; warp tile 32x64. Softmax warp-
// private (exp2 domain). P packed straight from S accumulators into fp16
// a-fragments. Q/K: [row][pair-permuted half2 of d]; V^T: halves j-permuted.
// ---------------------------------------------------------------------------
#define FSTR 40
#define QROWS 256
#define FLASH_SMEM ((QROWS + 64 + 64) * FSTR * 4)   // 61440 B

__global__ __launch_bounds__(256) void flash_f16(const float* __restrict__ qkv,
                                                 float* __restrict__ out)
{
    extern __shared__ uint32_t smu[];
    uint32_t* Qt = smu;                  // [256 r][FSTR]
    uint32_t* Kt = Qt + QROWS * FSTR;    // [64 j][FSTR]
    uint32_t* Vt = Kt + 64 * FSTR;       // [64 d][FSTR]  (V^T, j-pairs in half2)

    const int tid  = threadIdx.x;
    const int lane = tid & 31;
    const int wid  = tid >> 5;          // 0..7
    const int wm   = wid * 32;
    const int gid  = lane >> 2;
    const int tig  = lane & 3;
    const int qt   = gridDim.x - 1 - blockIdx.x;  // heavy blocks first
    const int h    = blockIdx.y;
    const int b    = blockIdx.z;

    // --- Q tile: 1 thread/row, scale by SCALE*log2e, fp16 pair-permuted ---
    {
        const float* qrow = qkv + ((size_t)(b * SEQ + qt * QROWS + tid)) * QKV_N + h * HEAD_DIM;
        #pragma unroll
        for (int it = 0; it < 16; it++) {
            float4 v = *(const float4*)(qrow + it * 4);
            Qt[tid * FSTR + pslot(2 * it)]     = pack_h2(v.x * SCALE_LOG2E, v.y * SCALE_LOG2E);
            Qt[tid * FSTR + pslot(2 * it + 1)] = pack_h2(v.z * SCALE_LOG2E, v.w * SCALE_LOG2E);
        }
    }

    // --- K/V register prefetch (4 threads/row, 16 els each) ---
    const int r63 = tid & 63;
    const int cg0 = tid >> 6;           // 0..3
    float4 ka[4], va[4];
    {
        const float* kb = qkv + ((size_t)(b * SEQ + r63)) * QKV_N + D_MODEL + h * HEAD_DIM;
        #pragma unroll
        for (int it = 0; it < 4; it++) {
            const int d4 = cg0 * 16 + it * 4;
            ka[it] = *(const float4*)(kb + d4);
            va[it] = *(const float4*)(kb + D_MODEL + d4);
        }
    }

    float co[2][8][4] = {};    // O fragments: 2 m-subtiles x 8 d-tiles
    float m[4], l[4];          // [s*2+g]: subtile s, row-group g (gid / gid+8)
    #pragma unroll
    for (int i = 0; i < 4; i++) { m[i] = -1e30f; l[i] = 0.f; }

    const int rbase = qt * QROWS + wm + gid;
    const int ktmax = 4 * qt + 3;
    __half* Vh = (__half*)Vt;
    const int vcol = 2 * pslot(r63 >> 1) + (r63 & 1);   // half column within V row

    for (int kt = 0; kt <= ktmax; kt++) {
        __syncthreads();  // previous tile's consumers done with Kt/Vt

        // store K (pair-permuted half2 of d) and V^T (halves, j-permuted)
        #pragma unroll
        for (int it = 0; it < 4; it++) {
            const int d4 = cg0 * 16 + it * 4;
            const int p0 = d4 >> 1;
            Kt[r63 * FSTR + pslot(p0)]     = pack_h2(ka[it].x, ka[it].y);
            Kt[r63 * FSTR + pslot(p0 + 1)] = pack_h2(ka[it].z, ka[it].w);
            Vh[(d4 + 0) * (2 * FSTR) + vcol] = __float2half_rn(va[it].x);
            Vh[(d4 + 1) * (2 * FSTR) + vcol] = __float2half_rn(va[it].y);
            Vh[(d4 + 2) * (2 * FSTR) + vcol] = __float2half_rn(va[it].z);
            Vh[(d4 + 3) * (2 * FSTR) + vcol] = __float2half_rn(va[it].w);
        }
        __syncthreads();

        // prefetch next K/V tile into registers
        if (kt < ktmax) {
            const float* kb = qkv + ((size_t)(b * SEQ + (kt + 1) * 64 + r63)) * QKV_N
                              + D_MODEL + h * HEAD_DIM;
            #pragma unroll
            for (int it = 0; it < 4; it++) {
                const int d4 = cg0 * 16 + it * 4;
                ka[it] = *(const float4*)(kb + d4);
                va[it] = *(const float4*)(kb + D_MODEL + d4);
            }
        }

        // --- S = Q K^T (log2-domain scores), 4 k16-steps ---
        float cs[2][8][4] = {};
        #pragma unroll
        for (int ks = 0; ks < 4; ks++) {
            uint32_t af[2][4];
            #pragma unroll
            for (int s = 0; s < 2; s++) {
                const uint2 qlo = *(const uint2*)&Qt[(wm + s * 16 + gid) * FSTR + ks * 8 + 2 * tig];
                const uint2 qhi = *(const uint2*)&Qt[(wm + s * 16 + gid + 8) * FSTR + ks * 8 + 2 * tig];
                af[s][0] = qlo.x; af[s][1] = qhi.x;
                af[s][2] = qlo.y; af[s][3] = qhi.y;
            }
            #pragma unroll
            for (int nt = 0; nt < 8; nt++) {
                const uint2 kb2 = *(const uint2*)&Kt[(nt * 8 + gid) * FSTR + ks * 8 + 2 * tig];
                uint32_t bf[2] = { kb2.x, kb2.y };
                mma_f16(cs[0][nt], af[0], bf);
                mma_f16(cs[1][nt], af[1], bf);
            }
        }

        // --- causal mask (diagonal-band tiles only) ---
        if (kt >= 4 * qt) {
            #pragma unroll
            for (int s = 0; s < 2; s++) {
                const int r0 = rbase + s * 16;
                const int r1 = r0 + 8;
                #pragma unroll
                for (int nt = 0; nt < 8; nt++) {
                    const int j0 = kt * 64 + nt * 8 + 2 * tig;
                    if (j0     > r0) cs[s][nt][0] = -1e30f;
                    if (j0 + 1 > r0) cs[s][nt][1] = -1e30f;
                    if (j0     > r1) cs[s][nt][2] = -1e30f;
                    if (j0 + 1 > r1) cs[s][nt][3] = -1e30f;
                }
            }
        }

        // --- warp-private online softmax (exp2 domain, quad reductions) ---
        #pragma unroll
        for (int s = 0; s < 2; s++) {
            float tm0 = -1e30f, tm1 = -1e30f;
            #pragma unroll
            for (int nt = 0; nt < 8; nt++) {
                tm0 = fmaxf(tm0, fmaxf(cs[s][nt][0], cs[s][nt][1]));
                tm1 = fmaxf(tm1, fmaxf(cs[s][nt][2], cs[s][nt][3]));
            }
            tm0 = fmaxf(tm0, __shfl_xor_sync(0xFFFFFFFFu, tm0, 1));
            tm0 = fmaxf(tm0, __shfl_xor_sync(0xFFFFFFFFu, tm0, 2));
            tm1 = fmaxf(tm1, __shfl_xor_sync(0xFFFFFFFFu, tm1, 1));
            tm1 = fmaxf(tm1, __shfl_xor_sync(0xFFFFFFFFu, tm1, 2));

            const float mn0 = fmaxf(m[s * 2 + 0], tm0);
            const float mn1 = fmaxf(m[s * 2 + 1], tm1);
            const float al0 = fexp2(m[s * 2 + 0] - mn0);
            const float al1 = fexp2(m[s * 2 + 1] - mn1);
            m[s * 2 + 0] = mn0; m[s * 2 + 1] = mn1;

            float rs0 = 0.f, rs1 = 0.f;
            #pragma unroll
            for (int nt = 0; nt < 8; nt++) {
                cs[s][nt][0] = fexp2(cs[s][nt][0] - mn0);
                cs[s][nt][1] = fexp2(cs[s][nt][1] - mn0);
                cs[s][nt][2] = fexp2(cs[s][nt][2] - mn1);
                cs[s][nt][3] = fexp2(cs[s][nt][3] - mn1);
                rs0 += cs[s][nt][0] + cs[s][nt][1];
                rs1 += cs[s][nt][2] + cs[s][nt][3];
            }
            rs0 += __shfl_xor_sync(0xFFFFFFFFu, rs0, 1);
            rs0 += __shfl_xor_sync(0xFFFFFFFFu, rs0, 2);
            rs1 += __shfl_xor_sync(0xFFFFFFFFu, rs1, 1);
            rs1 += __shfl_xor_sync(0xFFFFFFFFu, rs1, 2);
            l[s * 2 + 0] = l[s * 2 + 0] * al0 + rs0;
            l[s * 2 + 1] = l[s * 2 + 1] * al1 + rs1;

            #pragma unroll
            for (int nt = 0; nt < 8; nt++) {
                co[s][nt][0] *= al0; co[s][nt][1] *= al0;
                co[s][nt][2] *= al1; co[s][nt][3] *= al1;
            }
        }

        // --- O += P V: P packed from S accumulators (fp16 a-fragments) ---
        #pragma unroll
        for (int ks = 0; ks < 4; ks++) {
            uint32_t pf[2][4];
            #pragma unroll
            for (int s = 0; s < 2; s++) {
                pf[s][0] = pack_h2(cs[s][2 * ks][0],     cs[s][2 * ks][1]);
                pf[s][1] = pack_h2(cs[s][2 * ks][2],     cs[s][2 * ks][3]);
                pf[s][2] = pack_h2(cs[s][2 * ks + 1][0], cs[s][2 * ks + 1][1]);
                pf[s][3] = pack_h2(cs[s][2 * ks + 1][2], cs[s][2 * ks + 1][3]);
            }
            #pragma unroll
            for (int nt = 0; nt < 8; nt++) {
                const uint2 vb2 = *(const uint2*)&Vt[(nt * 8 + gid) * FSTR + ks * 8 + 2 * tig];
                uint32_t bf[2] = { vb2.x, vb2.y };
                mma_f16(co[0][nt], pf[0], bf);
                mma_f16(co[1][nt], pf[1], bf);
            }
        }
    }

    // --- epilogue ---
    float* ob = out + ((size_t)(b * SEQ + qt * QROWS)) * D_MODEL + h * HEAD_DIM;
    #pragma unroll
    for (int s = 0; s < 2; s++) {
        const float inv0 = 1.f / l[s * 2 + 0];
        const float inv1 = 1.f / l[s * 2 + 1];
        #pragma unroll
        for (int nt = 0; nt < 8; nt++) {
            const int cc = nt * 8 + 2 * tig;
            float2 v0 = make_float2(co[s][nt][0] * inv0, co[s][nt][1] * inv0);
            float2 v1 = make_float2(co[s][nt][2] * inv1, co[s][nt][3] * inv1);
            *(float2*)&ob[(size_t)(wm + s * 16 + gid) * D_MODEL + cc]     = v0;
            *(float2*)&ob[(size_t)(wm + s * 16 + gid + 8) * D_MODEL + cc] = v1;
        }
    }
}

// ---------------------------------------------------------------------------
// Launch: tf32 QKV GEMM -> fp16 flash attention -> tf32 out projection (+bias)
// Inputs: x, attn_mask (ignored; causal known), W_qkv, W_proj, b_proj
// ---------------------------------------------------------------------------
extern "C" void kernel_launch(void* const* d_in, const int* in_sizes, int n_in,
                              void* d_out, int out_size)
{
    (void)in_sizes; (void)n_in; (void)out_size;
    const float* x      = (const float*)d_in[0];
    const float* W_qkv  = (const float*)d_in[2];
    const float* W_proj = (const float*)d_in[3];
    const float* b_proj = (const float*)d_in[4];
    float* out = (float*)d_out;

    float *qkv, *attn;
    cudaGetSymbolAddress((void**)&qkv,  g_qkv);
    cudaGetSymbolAddress((void**)&attn, g_attn);

    cudaFuncSetAttribute(gemm_tf32, cudaFuncAttributeMaxDynamicSharedMemorySize, GEMM_SMEM);
    cudaFuncSetAttribute(flash_f16, cudaFuncAttributeMaxDynamicSharedMemorySize, FLASH_SMEM);

    // 1) QKV projection: [4096,768] @ [768,2304]  (tf32 tensor cores)
    gemm_tf32<<<dim3(QKV_N / 128, M_TOK / 128), 128, GEMM_SMEM>>>(x, W_qkv, nullptr, qkv,
                                                                  M_TOK, QKV_N, D_MODEL);

    // 2) causal flash attention per (q-tile, head, batch)  (fp16 tensor cores)
    flash_f16<<<dim3(SEQ / QROWS, N_HEADS, BATCH), 256, FLASH_SMEM>>>(qkv, attn);

    // 3) output projection + bias: [4096,768] @ [768,768]  (tf32 tensor cores)
    gemm_tf32<<<dim3(D_MODEL / 128, M_TOK / 128), 128, GEMM_SMEM>>>(attn, W_proj, b_proj, out,
                                                                    M_TOK, D_MODEL, D_MODEL);
}

// round 16
// speedup vs baseline: 1.5433x; 1.1974x over previous
#include <cuda_runtime.h>
#include <cuda_fp16.h>
#include <math.h>
#include <stdint.h>

#define D_MODEL 768
#define N_HEADS 12
#define HEAD_DIM 64
#define SEQ 2048
#define BATCH 2
#define QKV_N (3 * D_MODEL)
#define M_TOK (BATCH * SEQ)
#define SCALE_LOG2E 0.18033688011112042f   // 0.125 * log2(e)

// Scratch (allocation-free rule: __device__ globals)
__device__ float g_qkv[(size_t)M_TOK * QKV_N];    // [B*S, 3*D] (Q | K | V)
__device__ float g_attn[(size_t)M_TOK * D_MODEL]; // [B*S, D] attention output

__device__ __forceinline__ uint32_t pack_h2(float lo, float hi) {
    __half2 h = __floats2half2_rn(lo, hi);
    return *reinterpret_cast<uint32_t*>(&h);
}

__device__ __forceinline__ float fexp2(float x) {
    float r;
    asm("ex2.approx.f32 %0, %1;" : "=f"(r) : "f"(x));
    return r;
}

// fp16 mma m16n8k16, fp32 accumulate
__device__ __forceinline__ void mma_f16(float* c, const uint32_t* a, const uint32_t* b) {
    asm volatile("mma.sync.aligned.m16n8k16.row.col.f32.f16.f16.f32 "
                 "{%0,%1,%2,%3}, {%4,%5,%6,%7}, {%8,%9}, {%0,%1,%2,%3};"
                 : "+f"(c[0]), "+f"(c[1]), "+f"(c[2]), "+f"(c[3])
                 : "r"(a[0]), "r"(a[1]), "r"(a[2]), "r"(a[3]),
                   "r"(b[0]), "r"(b[1]));
}

// permuted slot for pair p within each group of 8:
// [p0 p4 p1 p5 p2 p6 p3 p7] -> pairs (t, t+4) adjacent -> uint2 loads
__device__ __host__ constexpr int pslot(int p) {
    return 8 * (p >> 3) + (((p & 7) < 4) ? 2 * (p & 7) : 2 * (p & 7) - 7);
}

// ---------------------------------------------------------------------------
// fp16 tensor-core GEMM v2: block 128x128x16, 128 threads = 4 warps (2Mx2N),
// warp tile 64x64, one m16n8k16 step per tile, double-buffered.
// A: [row][pair-permuted half2 of k] stride 24  (conflict-free uint2 frags).
// B: [k-pair][n] half2, stride 136 -> uint4 STS (conflict-free) and
//    LDS.32 frag reads at banks tig*8+gid (all distinct).
// ---------------------------------------------------------------------------
#define BKG 16
#define AF_STRIDE 24                     // uint32 per A row (8 used)
#define BF_STRIDE 136                    // uint32 per B k-pair row (128 used)
#define AF_TILE (128 * AF_STRIDE)        // 3072 words
#define BF_TILE (8 * BF_STRIDE)          // 1088 words
#define GEMM_SMEM ((2 * AF_TILE + 2 * BF_TILE) * 4)   // 33280 B

__global__ __launch_bounds__(128) void gemm_f16(const float* __restrict__ A,
                                                const float* __restrict__ B,
                                                const float* __restrict__ bias,
                                                float* __restrict__ C,
                                                int M, int N, int K)
{
    extern __shared__ uint32_t smu[];
    uint32_t* As0 = smu;
    uint32_t* As1 = As0 + AF_TILE;
    uint32_t* Bs0 = As1 + AF_TILE;
    uint32_t* Bs1 = Bs0 + BF_TILE;

    const int tid  = threadIdx.x;
    const int lane = tid & 31;
    const int wid  = tid >> 5;        // 0..3
    const int wm   = (wid & 1) * 64;
    const int wn   = (wid >> 1) * 64;
    const int row0 = blockIdx.y * 128;
    const int col0 = blockIdx.x * 128;
    const int gid  = lane >> 2;
    const int tig  = lane & 3;

    // A: 128x16 fp32 = 512 float4, 4/thread
    const float* Ag[4];
    int as0[4], as1[4];
    #pragma unroll
    for (int i = 0; i < 4; i++) {
        const int idx = tid + i * 128;
        const int ar  = idx >> 2;
        const int ak4 = (idx & 3) * 4;
        Ag[i]  = A + (size_t)(row0 + ar) * K + ak4;
        as0[i] = ar * AF_STRIDE + pslot(ak4 >> 1);
        as1[i] = ar * AF_STRIDE + pslot((ak4 >> 1) + 1);
    }
    // B: 8 k-pairs x 32 n4-groups = 256 units, 2 units/thread; each unit reads
    // rows 2kp & 2kp+1 (float4 each), packs 4 half2, stores ONE uint4.
    const float* Bg[2];
    int bs[2];
    #pragma unroll
    for (int i = 0; i < 2; i++) {
        const int u  = tid + i * 128;
        const int kp = u >> 5;
        const int n4 = (u & 31) * 4;
        Bg[i] = B + (size_t)(2 * kp) * N + col0 + n4;
        bs[i] = kp * BF_STRIDE + n4;
    }

    float4 pa[4], pbl[2], pbh[2];
    #pragma unroll
    for (int i = 0; i < 4; i++) pa[i] = *(const float4*)Ag[i];
    #pragma unroll
    for (int i = 0; i < 2; i++) {
        pbl[i] = *(const float4*)Bg[i];
        pbh[i] = *(const float4*)(Bg[i] + N);
    }
    #pragma unroll
    for (int i = 0; i < 4; i++) {
        As0[as0[i]] = pack_h2(pa[i].x, pa[i].y);
        As0[as1[i]] = pack_h2(pa[i].z, pa[i].w);
    }
    #pragma unroll
    for (int i = 0; i < 2; i++) {
        uint4 u;
        u.x = pack_h2(pbl[i].x, pbh[i].x);
        u.y = pack_h2(pbl[i].y, pbh[i].y);
        u.z = pack_h2(pbl[i].z, pbh[i].z);
        u.w = pack_h2(pbl[i].w, pbh[i].w);
        *(uint4*)&Bs0[bs[i]] = u;
    }
    __syncthreads();

    float c[4][8][4] = {};
    const int nkt = K / BKG;
    uint32_t *Acur = As0, *Anxt = As1, *Bcur = Bs0, *Bnxt = Bs1;

    for (int t = 0; t < nkt; t++) {
        if (t + 1 < nkt) {
            #pragma unroll
            for (int i = 0; i < 4; i++)
                pa[i] = *(const float4*)(Ag[i] + (t + 1) * BKG);
            #pragma unroll
            for (int i = 0; i < 2; i++) {
                pbl[i] = *(const float4*)(Bg[i] + (size_t)(t + 1) * BKG * N);
                pbh[i] = *(const float4*)(Bg[i] + (size_t)(t + 1) * BKG * N + N);
            }
        }

        // one k16 step: 32 mma
        {
            uint32_t af[4][4], bf[8][2];
            const uint32_t* Ap = Acur + (wm + gid) * AF_STRIDE + 2 * tig;
            #pragma unroll
            for (int mt = 0; mt < 4; mt++) {
                const uint2 lo = *(const uint2*)(Ap + mt * 16 * AF_STRIDE);
                const uint2 hi = *(const uint2*)(Ap + mt * 16 * AF_STRIDE + 8 * AF_STRIDE);
                af[mt][0] = lo.x; af[mt][1] = hi.x;
                af[mt][2] = lo.y; af[mt][3] = hi.y;
            }
            const uint32_t* Bp = Bcur + tig * BF_STRIDE + wn + gid;
            #pragma unroll
            for (int nt = 0; nt < 8; nt++) {
                bf[nt][0] = Bp[nt * 8];
                bf[nt][1] = Bp[4 * BF_STRIDE + nt * 8];
            }
            #pragma unroll
            for (int mt = 0; mt < 4; mt++)
                #pragma unroll
                for (int nt = 0; nt < 8; nt++)
                    mma_f16(c[mt][nt], af[mt], bf[nt]);
        }

        if (t + 1 < nkt) {
            #pragma unroll
            for (int i = 0; i < 4; i++) {
                Anxt[as0[i]] = pack_h2(pa[i].x, pa[i].y);
                Anxt[as1[i]] = pack_h2(pa[i].z, pa[i].w);
            }
            #pragma unroll
            for (int i = 0; i < 2; i++) {
                uint4 u;
                u.x = pack_h2(pbl[i].x, pbh[i].x);
                u.y = pack_h2(pbl[i].y, pbh[i].y);
                u.z = pack_h2(pbl[i].z, pbh[i].z);
                u.w = pack_h2(pbl[i].w, pbh[i].w);
                *(uint4*)&Bnxt[bs[i]] = u;
            }
            __syncthreads();
            uint32_t* tmp;
            tmp = Acur; Acur = Anxt; Anxt = tmp;
            tmp = Bcur; Bcur = Bnxt; Bnxt = tmp;
        }
    }

    #pragma unroll
    for (int nt = 0; nt < 8; nt++) {
        const int cc = col0 + wn + nt * 8 + 2 * tig;
        const float b0 = bias ? bias[cc]     : 0.f;
        const float b1 = bias ? bias[cc + 1] : 0.f;
        #pragma unroll
        for (int mt = 0; mt < 4; mt++) {
            const int r = row0 + wm + mt * 16 + gid;
            float2 v0 = make_float2(c[mt][nt][0] + b0, c[mt][nt][1] + b1);
            float2 v1 = make_float2(c[mt][nt][2] + b0, c[mt][nt][3] + b1);
            *(float2*)&C[(size_t)r * N + cc]       = v0;
            *(float2*)&C[(size_t)(r + 8) * N + cc] = v1;
        }
    }
}

// ---------------------------------------------------------------------------
// FA2-style fp16 flash attention (round-13/14 measured best: ~167us).
// 256 threads = 8 warps; Q tile 256 rows; warp tile 32x64. Softmax warp-
// private (exp2 domain). P packed straight from S accumulators into fp16
// a-fragments. Q/K: [row][pair-permuted half2 of d]; V^T: halves j-permuted.
// ---------------------------------------------------------------------------
#define FSTR 40
#define QROWS 256
#define FLASH_SMEM ((QROWS + 64 + 64) * FSTR * 4)   // 61440 B

__global__ __launch_bounds__(256) void flash_f16(const float* __restrict__ qkv,
                                                 float* __restrict__ out)
{
    extern __shared__ uint32_t smu[];
    uint32_t* Qt = smu;                  // [256 r][FSTR]
    uint32_t* Kt = Qt + QROWS * FSTR;    // [64 j][FSTR]
    uint32_t* Vt = Kt + 64 * FSTR;       // [64 d][FSTR]  (V^T, j-pairs in half2)

    const int tid  = threadIdx.x;
    const int lane = tid & 31;
    const int wid  = tid >> 5;          // 0..7
    const int wm   = wid * 32;
    const int gid  = lane >> 2;
    const int tig  = lane & 3;
    const int qt   = gridDim.x - 1 - blockIdx.x;  // heavy blocks first
    const int h    = blockIdx.y;
    const int b    = blockIdx.z;

    // --- Q tile: 1 thread/row, scale by SCALE*log2e, fp16 pair-permuted ---
    {
        const float* qrow = qkv + ((size_t)(b * SEQ + qt * QROWS + tid)) * QKV_N + h * HEAD_DIM;
        #pragma unroll
        for (int it = 0; it < 16; it++) {
            float4 v = *(const float4*)(qrow + it * 4);
            Qt[tid * FSTR + pslot(2 * it)]     = pack_h2(v.x * SCALE_LOG2E, v.y * SCALE_LOG2E);
            Qt[tid * FSTR + pslot(2 * it + 1)] = pack_h2(v.z * SCALE_LOG2E, v.w * SCALE_LOG2E);
        }
    }

    // --- K/V register prefetch (4 threads/row, 16 els each) ---
    const int r63 = tid & 63;
    const int cg0 = tid >> 6;           // 0..3
    float4 ka[4], va[4];
    {
        const float* kb = qkv + ((size_t)(b * SEQ + r63)) * QKV_N + D_MODEL + h * HEAD_DIM;
        #pragma unroll
        for (int it = 0; it < 4; it++) {
            const int d4 = cg0 * 16 + it * 4;
            ka[it] = *(const float4*)(kb + d4);
            va[it] = *(const float4*)(kb + D_MODEL + d4);
        }
    }

    float co[2][8][4] = {};    // O fragments: 2 m-subtiles x 8 d-tiles
    float m[4], l[4];          // [s*2+g]: subtile s, row-group g (gid / gid+8)
    #pragma unroll
    for (int i = 0; i < 4; i++) { m[i] = -1e30f; l[i] = 0.f; }

    const int rbase = qt * QROWS + wm + gid;
    const int ktmax = 4 * qt + 3;
    __half* Vh = (__half*)Vt;
    const int vcol = 2 * pslot(r63 >> 1) + (r63 & 1);   // half column within V row

    for (int kt = 0; kt <= ktmax; kt++) {
        __syncthreads();  // previous tile's consumers done with Kt/Vt

        // store K (pair-permuted half2 of d) and V^T (halves, j-permuted)
        #pragma unroll
        for (int it = 0; it < 4; it++) {
            const int d4 = cg0 * 16 + it * 4;
            const int p0 = d4 >> 1;
            Kt[r63 * FSTR + pslot(p0)]     = pack_h2(ka[it].x, ka[it].y);
            Kt[r63 * FSTR + pslot(p0 + 1)] = pack_h2(ka[it].z, ka[it].w);
            Vh[(d4 + 0) * (2 * FSTR) + vcol] = __float2half_rn(va[it].x);
            Vh[(d4 + 1) * (2 * FSTR) + vcol] = __float2half_rn(va[it].y);
            Vh[(d4 + 2) * (2 * FSTR) + vcol] = __float2half_rn(va[it].z);
            Vh[(d4 + 3) * (2 * FSTR) + vcol] = __float2half_rn(va[it].w);
        }
        __syncthreads();

        // prefetch next K/V tile into registers
        if (kt < ktmax) {
            const float* kb = qkv + ((size_t)(b * SEQ + (kt + 1) * 64 + r63)) * QKV_N
                              + D_MODEL + h * HEAD_DIM;
            #pragma unroll
            for (int it = 0; it < 4; it++) {
                const int d4 = cg0 * 16 + it * 4;
                ka[it] = *(const float4*)(kb + d4);
                va[it] = *(const float4*)(kb + D_MODEL + d4);
            }
        }

        // --- S = Q K^T (log2-domain scores), 4 k16-steps ---
        float cs[2][8][4] = {};
        #pragma unroll
        for (int ks = 0; ks < 4; ks++) {
            uint32_t af[2][4];
            #pragma unroll
            for (int s = 0; s < 2; s++) {
                const uint2 qlo = *(const uint2*)&Qt[(wm + s * 16 + gid) * FSTR + ks * 8 + 2 * tig];
                const uint2 qhi = *(const uint2*)&Qt[(wm + s * 16 + gid + 8) * FSTR + ks * 8 + 2 * tig];
                af[s][0] = qlo.x; af[s][1] = qhi.x;
                af[s][2] = qlo.y; af[s][3] = qhi.y;
            }
            #pragma unroll
            for (int nt = 0; nt < 8; nt++) {
                const uint2 kb2 = *(const uint2*)&Kt[(nt * 8 + gid) * FSTR + ks * 8 + 2 * tig];
                uint32_t bf[2] = { kb2.x, kb2.y };
                mma_f16(cs[0][nt], af[0], bf);
                mma_f16(cs[1][nt], af[1], bf);
            }
        }

        // --- causal mask (diagonal-band tiles only) ---
        if (kt >= 4 * qt) {
            #pragma unroll
            for (int s = 0; s < 2; s++) {
                const int r0 = rbase + s * 16;
                const int r1 = r0 + 8;
                #pragma unroll
                for (int nt = 0; nt < 8; nt++) {
                    const int j0 = kt * 64 + nt * 8 + 2 * tig;
                    if (j0     > r0) cs[s][nt][0] = -1e30f;
                    if (j0 + 1 > r0) cs[s][nt][1] = -1e30f;
                    if (j0     > r1) cs[s][nt][2] = -1e30f;
                    if (j0 + 1 > r1) cs[s][nt][3] = -1e30f;
                }
            }
        }

        // --- warp-private online softmax (exp2 domain, quad reductions) ---
        #pragma unroll
        for (int s = 0; s < 2; s++) {
            float tm0 = -1e30f, tm1 = -1e30f;
            #pragma unroll
            for (int nt = 0; nt < 8; nt++) {
                tm0 = fmaxf(tm0, fmaxf(cs[s][nt][0], cs[s][nt][1]));
                tm1 = fmaxf(tm1, fmaxf(cs[s][nt][2], cs[s][nt][3]));
            }
            tm0 = fmaxf(tm0, __shfl_xor_sync(0xFFFFFFFFu, tm0, 1));
            tm0 = fmaxf(tm0, __shfl_xor_sync(0xFFFFFFFFu, tm0, 2));
            tm1 = fmaxf(tm1, __shfl_xor_sync(0xFFFFFFFFu, tm1, 1));
            tm1 = fmaxf(tm1, __shfl_xor_sync(0xFFFFFFFFu, tm1, 2));

            const float mn0 = fmaxf(m[s * 2 + 0], tm0);
            const float mn1 = fmaxf(m[s * 2 + 1], tm1);
            const float al0 = fexp2(m[s * 2 + 0] - mn0);
            const float al1 = fexp2(m[s * 2 + 1] - mn1);
            m[s * 2 + 0] = mn0; m[s * 2 + 1] = mn1;

            float rs0 = 0.f, rs1 = 0.f;
            #pragma unroll
            for (int nt = 0; nt < 8; nt++) {
                cs[s][nt][0] = fexp2(cs[s][nt][0] - mn0);
                cs[s][nt][1] = fexp2(cs[s][nt][1] - mn0);
                cs[s][nt][2] = fexp2(cs[s][nt][2] - mn1);
                cs[s][nt][3] = fexp2(cs[s][nt][3] - mn1);
                rs0 += cs[s][nt][0] + cs[s][nt][1];
                rs1 += cs[s][nt][2] + cs[s][nt][3];
            }
            rs0 += __shfl_xor_sync(0xFFFFFFFFu, rs0, 1);
            rs0 += __shfl_xor_sync(0xFFFFFFFFu, rs0, 2);
            rs1 += __shfl_xor_sync(0xFFFFFFFFu, rs1, 1);
            rs1 += __shfl_xor_sync(0xFFFFFFFFu, rs1, 2);
            l[s * 2 + 0] = l[s * 2 + 0] * al0 + rs0;
            l[s * 2 + 1] = l[s * 2 + 1] * al1 + rs1;

            #pragma unroll
            for (int nt = 0; nt < 8; nt++) {
                co[s][nt][0] *= al0; co[s][nt][1] *= al0;
                co[s][nt][2] *= al1; co[s][nt][3] *= al1;
            }
        }

        // --- O += P V: P packed from S accumulators (fp16 a-fragments) ---
        #pragma unroll
        for (int ks = 0; ks < 4; ks++) {
            uint32_t pf[2][4];
            #pragma unroll
            for (int s = 0; s < 2; s++) {
                pf[s][0] = pack_h2(cs[s][2 * ks][0],     cs[s][2 * ks][1]);
                pf[s][1] = pack_h2(cs[s][2 * ks][2],     cs[s][2 * ks][3]);
                pf[s][2] = pack_h2(cs[s][2 * ks + 1][0], cs[s][2 * ks + 1][1]);
                pf[s][3] = pack_h2(cs[s][2 * ks + 1][2], cs[s][2 * ks + 1][3]);
            }
            #pragma unroll
            for (int nt = 0; nt < 8; nt++) {
                const uint2 vb2 = *(const uint2*)&Vt[(nt * 8 + gid) * FSTR + ks * 8 + 2 * tig];
                uint32_t bf[2] = { vb2.x, vb2.y };
                mma_f16(co[0][nt], pf[0], bf);
                mma_f16(co[1][nt], pf[1], bf);
            }
        }
    }

    // --- epilogue ---
    float* ob = out + ((size_t)(b * SEQ + qt * QROWS)) * D_MODEL + h * HEAD_DIM;
    #pragma unroll
    for (int s = 0; s < 2; s++) {
        const float inv0 = 1.f / l[s * 2 + 0];
        const float inv1 = 1.f / l[s * 2 + 1];
        #pragma unroll
        for (int nt = 0; nt < 8; nt++) {
            const int cc = nt * 8 + 2 * tig;
            float2 v0 = make_float2(co[s][nt][0] * inv0, co[s][nt][1] * inv0);
            float2 v1 = make_float2(co[s][nt][2] * inv1, co[s][nt][3] * inv1);
            *(float2*)&ob[(size_t)(wm + s * 16 + gid) * D_MODEL + cc]     = v0;
            *(float2*)&ob[(size_t)(wm + s * 16 + gid + 8) * D_MODEL + cc] = v1;
        }
    }
}

// ---------------------------------------------------------------------------
// Launch: fp16 QKV GEMM -> fp16 flash attention -> fp16 out projection (+bias)
// Inputs: x, attn_mask (ignored; causal known), W_qkv, W_proj, b_proj
// ---------------------------------------------------------------------------
extern "C" void kernel_launch(void* const* d_in, const int* in_sizes, int n_in,
                              void* d_out, int out_size)
{
    (void)in_sizes; (void)n_in; (void)out_size;
    const float* x      = (const float*)d_in[0];
    const float* W_qkv  = (const float*)d_in[2];
    const float* W_proj = (const float*)d_in[3];
    const float* b_proj = (const float*)d_in[4];
    float* out = (float*)d_out;

    float *qkv, *attn;
    cudaGetSymbolAddress((void**)&qkv,  g_qkv);
    cudaGetSymbolAddress((void**)&attn, g_attn);

    cudaFuncSetAttribute(gemm_f16, cudaFuncAttributeMaxDynamicSharedMemorySize, GEMM_SMEM);
    cudaFuncSetAttribute(flash_f16, cudaFuncAttributeMaxDynamicSharedMemorySize, FLASH_SMEM);

    // 1) QKV projection: [4096,768] @ [768,2304]  (fp16 tensor cores)
    gemm_f16<<<dim3(QKV_N / 128, M_TOK / 128), 128, GEMM_SMEM>>>(x, W_qkv, nullptr, qkv,
                                                                 M_TOK, QKV_N, D_MODEL);

    // 2) causal flash attention per (q-tile, head, batch)  (fp16 tensor cores)
    flash_f16<<<dim3(SEQ / QROWS, N_HEADS, BATCH), 256, FLASH_SMEM>>>(qkv, attn);

    // 3) output projection + bias: [4096,768] @ [768,768]  (fp16 tensor cores)
    gemm_f16<<<dim3(D_MODEL / 128, M_TOK / 128), 128, GEMM_SMEM>>>(attn, W_proj, b_proj, out,
                                                                   M_TOK, D_MODEL, D_MODEL);
}